// round 1
// baseline (speedup 1.0000x reference)
#include <cuda_runtime.h>
#include <math.h>

#define TOK   8192
#define DM    1024
#define DQKV  3072
#define DFF   2048
#define NHEAD 16
#define SEQ   2048
#define BATCH 4

// ---------------- scratch (device globals: allocation-free) ----------------
__device__ float g_h  [TOK * DM];    // LN1 output
__device__ float g_qkv[TOK * DQKV];  // qkv projection
__device__ float g_ctx[TOK * DM];    // attention context
__device__ float g_x1 [TOK * DM];    // residual 1
__device__ float g_h2 [TOK * DM];    // LN2 output
__device__ float g_ff [TOK * DFF];   // ff1 output (post-GELU)

// ---------------- LayerNorm: one block per row of 1024 ----------------
__global__ void ln_kernel(const float* __restrict__ x,
                          const float* __restrict__ gam,
                          const float* __restrict__ bet,
                          float* __restrict__ out) {
    const int row = blockIdx.x;
    const int t   = threadIdx.x;
    const float* xr = x + (size_t)row * DM;
    const int c0 = t * 4;
    float4 v = *(const float4*)(xr + c0);

    float s  = v.x + v.y + v.z + v.w;
    float ss = v.x*v.x + v.y*v.y + v.z*v.z + v.w*v.w;
    #pragma unroll
    for (int o = 16; o; o >>= 1) {
        s  += __shfl_xor_sync(0xffffffffu, s,  o);
        ss += __shfl_xor_sync(0xffffffffu, ss, o);
    }
    __shared__ float sm[8], sm2[8];
    const int w = t >> 5;
    if ((t & 31) == 0) { sm[w] = s; sm2[w] = ss; }
    __syncthreads();
    if (w == 0) {
        float a = (t < 8) ? sm[t]  : 0.f;
        float c = (t < 8) ? sm2[t] : 0.f;
        a += __shfl_xor_sync(0xffffffffu, a, 1); c += __shfl_xor_sync(0xffffffffu, c, 1);
        a += __shfl_xor_sync(0xffffffffu, a, 2); c += __shfl_xor_sync(0xffffffffu, c, 2);
        a += __shfl_xor_sync(0xffffffffu, a, 4); c += __shfl_xor_sync(0xffffffffu, c, 4);
        if (t == 0) {
            float mu  = a * (1.0f / DM);
            float var = c * (1.0f / DM) - mu * mu;
            sm[0]  = mu;
            sm2[0] = rsqrtf(var + 1e-5f);
        }
    }
    __syncthreads();
    const float mu = sm[0], rs = sm2[0];
    float4 g4 = *(const float4*)(gam + c0);
    float4 b4 = *(const float4*)(bet + c0);
    float4 o4;
    o4.x = (v.x - mu) * rs * g4.x + b4.x;
    o4.y = (v.y - mu) * rs * g4.y + b4.y;
    o4.z = (v.z - mu) * rs * g4.z + b4.z;
    o4.w = (v.w - mu) * rs * g4.w + b4.w;
    *(float4*)(out + (size_t)row * DM + c0) = o4;
}

// ---------------- SGEMM 128x128x8, 256 threads, 8x8 microtile ----------------
// C[M,N] = A[M,K] @ B[K,N] + bias  (+residual | +GELU per EPI)
// EPI: 0 = bias, 1 = bias + residual, 2 = bias + exact GELU
template<int EPI>
__global__ __launch_bounds__(256)
void sgemm_kernel(const float* __restrict__ A, const float* __restrict__ B,
                  const float* __restrict__ bias, const float* __restrict__ res,
                  float* __restrict__ C, int M, int N, int K) {
    __shared__ float As[8][128];   // [k][m] (transposed)
    __shared__ float Bs[8][128];   // [k][n]
    const int tid = threadIdx.x;
    const int tx  = tid & 15;      // col lane
    const int ty  = tid >> 4;      // row lane
    const int rb  = blockIdx.y << 7;
    const int cb  = blockIdx.x << 7;

    float acc[8][8];
    #pragma unroll
    for (int i = 0; i < 8; i++)
        #pragma unroll
        for (int j = 0; j < 8; j++) acc[i][j] = 0.f;

    const int arow = tid >> 1;            // 0..127
    const int acol = (tid & 1) * 4;       // 0 or 4
    const int brow = tid >> 5;            // 0..7
    const int bcol = (tid & 31) * 4;      // 0..124

    const float* Aptr = A + (size_t)(rb + arow) * K + acol;
    const float* Bptr = B + (size_t)brow * N + cb + bcol;

    float4 aReg = *(const float4*)Aptr;
    float4 bReg = *(const float4*)Bptr;

    for (int k0 = 0; k0 < K; k0 += 8) {
        As[acol + 0][arow] = aReg.x;
        As[acol + 1][arow] = aReg.y;
        As[acol + 2][arow] = aReg.z;
        As[acol + 3][arow] = aReg.w;
        *(float4*)&Bs[brow][bcol] = bReg;
        __syncthreads();

        if (k0 + 8 < K) {   // prefetch next tile into registers (overlaps compute)
            aReg = *(const float4*)(Aptr + k0 + 8);
            bReg = *(const float4*)(Bptr + (size_t)(k0 + 8) * N);
        }

        #pragma unroll
        for (int kk = 0; kk < 8; kk++) {
            float a[8], b[8];
            #pragma unroll
            for (int i = 0; i < 8; i++) a[i] = As[kk][ty + i * 16];
            #pragma unroll
            for (int j = 0; j < 8; j++) b[j] = Bs[kk][tx + j * 16];
            #pragma unroll
            for (int i = 0; i < 8; i++)
                #pragma unroll
                for (int j = 0; j < 8; j++)
                    acc[i][j] += a[i] * b[j];
        }
        __syncthreads();
    }

    // epilogue
    #pragma unroll
    for (int i = 0; i < 8; i++) {
        const int r = rb + ty + i * 16;
        float* Crow = C + (size_t)r * N + cb;
        const float* Rrow = (EPI == 1) ? (res + (size_t)r * N + cb) : nullptr;
        #pragma unroll
        for (int j = 0; j < 8; j++) {
            const int c = tx + j * 16;
            float v = acc[i][j] + bias[cb + c];
            if (EPI == 1) v += Rrow[c];
            if (EPI == 2) v = 0.5f * v * (1.0f + erff(v * 0.70710678118654752f));
            Crow[c] = v;
        }
    }
}

// ---------------- Flash attention (fp32) ----------------
// grid: (SEQ/32, NHEAD, BATCH), block 256.
// Thread (ql, dc): ql = tid>>3 handles query q0+ql; dc = tid&7 owns d = i*8+dc.
__global__ __launch_bounds__(256)
void attn_kernel(const float* __restrict__ qkv, float* __restrict__ ctx) {
    const int b  = blockIdx.z;
    const int h  = blockIdx.y;
    const int q0 = blockIdx.x * 32;
    const int tid = threadIdx.x;
    const int ql = tid >> 3;
    const int dc = tid & 7;

    __shared__ float Ks[64][64];
    __shared__ float Vs[64][64];

    const size_t base = (size_t)b * SEQ * DQKV;
    const float* Qg = qkv + base + h * 64;
    const float* Kg = qkv + base + 1024 + h * 64;
    const float* Vg = qkv + base + 2048 + h * 64;

    const float scale = 0.125f;   // 1/sqrt(64)
    float qr[8];
    #pragma unroll
    for (int i = 0; i < 8; i++)
        qr[i] = Qg[(size_t)(q0 + ql) * DQKV + i * 8 + dc] * scale;

    float o[8];
    #pragma unroll
    for (int i = 0; i < 8; i++) o[i] = 0.f;
    float m = -1e30f, l = 0.f;

    for (int kt = 0; kt < SEQ; kt += 64) {
        // stage K,V tiles (64x64 each): 1024 float4, 256 threads -> 4 each
        #pragma unroll
        for (int j = 0; j < 4; j++) {
            int e  = tid + j * 256;
            int r  = e >> 4;
            int c4 = (e & 15) * 4;
            *(float4*)&Ks[r][c4] = *(const float4*)&Kg[(size_t)(kt + r) * DQKV + c4];
            *(float4*)&Vs[r][c4] = *(const float4*)&Vg[(size_t)(kt + r) * DQKV + c4];
        }
        __syncthreads();

        // S = q . k (partial over 8 owned d's), then 8-lane butterfly reduce
        float s[64];
        #pragma unroll
        for (int k = 0; k < 64; k++) {
            float p = 0.f;
            #pragma unroll
            for (int i = 0; i < 8; i++) p += qr[i] * Ks[k][i * 8 + dc];
            s[k] = p;
        }
        #pragma unroll
        for (int k = 0; k < 64; k++) {
            s[k] += __shfl_xor_sync(0xffffffffu, s[k], 1);
            s[k] += __shfl_xor_sync(0xffffffffu, s[k], 2);
            s[k] += __shfl_xor_sync(0xffffffffu, s[k], 4);
        }
        // online softmax (all 8 lanes hold identical full rows -> identical m,l)
        float mt = m;
        #pragma unroll
        for (int k = 0; k < 64; k++) mt = fmaxf(mt, s[k]);
        const float corr = __expf(m - mt);
        m = mt;
        l *= corr;
        #pragma unroll
        for (int i = 0; i < 8; i++) o[i] *= corr;

        float lsum = 0.f;
        #pragma unroll
        for (int k = 0; k < 64; k++) {
            s[k] = __expf(s[k] - m);
            lsum += s[k];
        }
        l += lsum;

        // O += P @ V  (each lane updates its owned d's)
        #pragma unroll
        for (int k = 0; k < 64; k++) {
            const float p = s[k];
            #pragma unroll
            for (int i = 0; i < 8; i++)
                o[i] += p * Vs[k][i * 8 + dc];
        }
        __syncthreads();
    }

    const float inv = 1.0f / l;
    float* Cp = ctx + ((size_t)b * SEQ + q0 + ql) * DM + h * 64;
    #pragma unroll
    for (int i = 0; i < 8; i++)
        Cp[i * 8 + dc] = o[i] * inv;
}

// ---------------- launch ----------------
extern "C" void kernel_launch(void* const* d_in, const int* in_sizes, int n_in,
                              void* d_out, int out_size) {
    const float* x     = (const float*)d_in[0];
    const float* qkv_w = (const float*)d_in[1];
    const float* qkv_b = (const float*)d_in[2];
    const float* out_w = (const float*)d_in[3];
    const float* out_b = (const float*)d_in[4];
    const float* ff1_w = (const float*)d_in[5];
    const float* ff1_b = (const float*)d_in[6];
    const float* ff2_w = (const float*)d_in[7];
    const float* ff2_b = (const float*)d_in[8];
    const float* ln1_g = (const float*)d_in[9];
    const float* ln1_b = (const float*)d_in[10];
    const float* ln2_g = (const float*)d_in[11];
    const float* ln2_b = (const float*)d_in[12];
    float* out = (float*)d_out;

    float *h, *qkv, *ctx, *x1, *h2, *ff;
    cudaGetSymbolAddress((void**)&h,   g_h);
    cudaGetSymbolAddress((void**)&qkv, g_qkv);
    cudaGetSymbolAddress((void**)&ctx, g_ctx);
    cudaGetSymbolAddress((void**)&x1,  g_x1);
    cudaGetSymbolAddress((void**)&h2,  g_h2);
    cudaGetSymbolAddress((void**)&ff,  g_ff);

    // 1. LN1
    ln_kernel<<<TOK, 256>>>(x, ln1_g, ln1_b, h);
    // 2. QKV projection [8192,1024]@[1024,3072]
    sgemm_kernel<0><<<dim3(DQKV / 128, TOK / 128), 256>>>(h, qkv_w, qkv_b, nullptr, qkv, TOK, DQKV, DM);
    // 3. attention
    attn_kernel<<<dim3(SEQ / 32, NHEAD, BATCH), 256>>>(qkv, ctx);
    // 4. out projection + residual  [8192,1024]@[1024,1024] + x
    sgemm_kernel<1><<<dim3(DM / 128, TOK / 128), 256>>>(ctx, out_w, out_b, x, x1, TOK, DM, DM);
    // 5. LN2
    ln_kernel<<<TOK, 256>>>(x1, ln2_g, ln2_b, h2);
    // 6. FF1 + GELU  [8192,1024]@[1024,2048]
    sgemm_kernel<2><<<dim3(DFF / 128, TOK / 128), 256>>>(h2, ff1_w, ff1_b, nullptr, ff, TOK, DFF, DM);
    // 7. FF2 + residual  [8192,2048]@[2048,1024] + x1 -> out
    sgemm_kernel<1><<<dim3(DM / 128, TOK / 128), 256>>>(ff, ff2_w, ff2_b, x1, out, TOK, DM, DFF);
}

// round 2
// speedup vs baseline: 1.0007x; 1.0007x over previous
#include <cuda_runtime.h>
#include <math.h>

#define TOK   8192
#define DM    1024
#define DQKV  3072
#define DFF   2048
#define NHEAD 16
#define SEQ   2048
#define BATCH 4

// ---------------- scratch (device globals: allocation-free) ----------------
__device__ float g_h  [TOK * DM];    // LN1 output
__device__ float g_qkv[TOK * DQKV];  // qkv projection
__device__ float g_ctx[TOK * DM];    // attention context
__device__ float g_x1 [TOK * DM];    // residual 1
__device__ float g_h2 [TOK * DM];    // LN2 output
__device__ float g_ff [TOK * DFF];   // ff1 output (post-GELU)

// ---------------- LayerNorm: one block per row of 1024 ----------------
__global__ void ln_kernel(const float* __restrict__ x,
                          const float* __restrict__ gam,
                          const float* __restrict__ bet,
                          float* __restrict__ out) {
    const int row = blockIdx.x;
    const int t   = threadIdx.x;
    const float* xr = x + (size_t)row * DM;
    const int c0 = t * 4;
    float4 v = *(const float4*)(xr + c0);

    float s  = v.x + v.y + v.z + v.w;
    float ss = v.x*v.x + v.y*v.y + v.z*v.z + v.w*v.w;
    #pragma unroll
    for (int o = 16; o; o >>= 1) {
        s  += __shfl_xor_sync(0xffffffffu, s,  o);
        ss += __shfl_xor_sync(0xffffffffu, ss, o);
    }
    __shared__ float sm[8], sm2[8];
    const int w = t >> 5;
    if ((t & 31) == 0) { sm[w] = s; sm2[w] = ss; }
    __syncthreads();
    if (w == 0) {
        float a = (t < 8) ? sm[t]  : 0.f;
        float c = (t < 8) ? sm2[t] : 0.f;
        a += __shfl_xor_sync(0xffffffffu, a, 1); c += __shfl_xor_sync(0xffffffffu, c, 1);
        a += __shfl_xor_sync(0xffffffffu, a, 2); c += __shfl_xor_sync(0xffffffffu, c, 2);
        a += __shfl_xor_sync(0xffffffffu, a, 4); c += __shfl_xor_sync(0xffffffffu, c, 4);
        if (t == 0) {
            float mu  = a * (1.0f / DM);
            float var = c * (1.0f / DM) - mu * mu;
            sm[0]  = mu;
            sm2[0] = rsqrtf(var + 1e-5f);
        }
    }
    __syncthreads();
    const float mu = sm[0], rs = sm2[0];
    float4 g4 = *(const float4*)(gam + c0);
    float4 b4 = *(const float4*)(bet + c0);
    float4 o4;
    o4.x = (v.x - mu) * rs * g4.x + b4.x;
    o4.y = (v.y - mu) * rs * g4.y + b4.y;
    o4.z = (v.z - mu) * rs * g4.z + b4.z;
    o4.w = (v.w - mu) * rs * g4.w + b4.w;
    *(float4*)(out + (size_t)row * DM + c0) = o4;
}

// ---------------- SGEMM 128x128x8, 256 threads, 8x8 microtile ----------------
// C[M,N] = A[M,K] @ B[K,N] + bias  (+residual | +GELU per EPI)
// EPI: 0 = bias, 1 = bias + residual, 2 = bias + exact GELU
template<int EPI>
__global__ __launch_bounds__(256)
void sgemm_kernel(const float* __restrict__ A, const float* __restrict__ B,
                  const float* __restrict__ bias, const float* __restrict__ res,
                  float* __restrict__ C, int M, int N, int K) {
    __shared__ float As[8][128];   // [k][m] (transposed)
    __shared__ float Bs[8][128];   // [k][n]
    const int tid = threadIdx.x;
    const int tx  = tid & 15;      // col lane
    const int ty  = tid >> 4;      // row lane
    const int rb  = blockIdx.y << 7;
    const int cb  = blockIdx.x << 7;

    float acc[8][8];
    #pragma unroll
    for (int i = 0; i < 8; i++)
        #pragma unroll
        for (int j = 0; j < 8; j++) acc[i][j] = 0.f;

    const int arow = tid >> 1;            // 0..127
    const int acol = (tid & 1) * 4;       // 0 or 4
    const int brow = tid >> 5;            // 0..7
    const int bcol = (tid & 31) * 4;      // 0..124

    const float* Aptr = A + (size_t)(rb + arow) * K + acol;
    const float* Bptr = B + (size_t)brow * N + cb + bcol;

    float4 aReg = *(const float4*)Aptr;
    float4 bReg = *(const float4*)Bptr;

    for (int k0 = 0; k0 < K; k0 += 8) {
        As[acol + 0][arow] = aReg.x;
        As[acol + 1][arow] = aReg.y;
        As[acol + 2][arow] = aReg.z;
        As[acol + 3][arow] = aReg.w;
        *(float4*)&Bs[brow][bcol] = bReg;
        __syncthreads();

        if (k0 + 8 < K) {   // prefetch next tile into registers (overlaps compute)
            aReg = *(const float4*)(Aptr + k0 + 8);
            bReg = *(const float4*)(Bptr + (size_t)(k0 + 8) * N);
        }

        #pragma unroll
        for (int kk = 0; kk < 8; kk++) {
            float a[8], b[8];
            #pragma unroll
            for (int i = 0; i < 8; i++) a[i] = As[kk][ty + i * 16];
            #pragma unroll
            for (int j = 0; j < 8; j++) b[j] = Bs[kk][tx + j * 16];
            #pragma unroll
            for (int i = 0; i < 8; i++)
                #pragma unroll
                for (int j = 0; j < 8; j++)
                    acc[i][j] += a[i] * b[j];
        }
        __syncthreads();
    }

    // epilogue
    #pragma unroll
    for (int i = 0; i < 8; i++) {
        const int r = rb + ty + i * 16;
        float* Crow = C + (size_t)r * N + cb;
        const float* Rrow = (EPI == 1) ? (res + (size_t)r * N + cb) : nullptr;
        #pragma unroll
        for (int j = 0; j < 8; j++) {
            const int c = tx + j * 16;
            float v = acc[i][j] + bias[cb + c];
            if (EPI == 1) v += Rrow[c];
            if (EPI == 2) v = 0.5f * v * (1.0f + erff(v * 0.70710678118654752f));
            Crow[c] = v;
        }
    }
}

// ---------------- Flash attention (fp32) ----------------
// grid: (SEQ/32, NHEAD, BATCH), block 256.
// Thread (ql, dc): ql = tid>>3 handles query q0+ql; dc = tid&7 owns d = i*8+dc.
__global__ __launch_bounds__(256)
void attn_kernel(const float* __restrict__ qkv, float* __restrict__ ctx) {
    const int b  = blockIdx.z;
    const int h  = blockIdx.y;
    const int q0 = blockIdx.x * 32;
    const int tid = threadIdx.x;
    const int ql = tid >> 3;
    const int dc = tid & 7;

    __shared__ float Ks[64][64];
    __shared__ float Vs[64][64];

    const size_t base = (size_t)b * SEQ * DQKV;
    const float* Qg = qkv + base + h * 64;
    const float* Kg = qkv + base + 1024 + h * 64;
    const float* Vg = qkv + base + 2048 + h * 64;

    const float scale = 0.125f;   // 1/sqrt(64)
    float qr[8];
    #pragma unroll
    for (int i = 0; i < 8; i++)
        qr[i] = Qg[(size_t)(q0 + ql) * DQKV + i * 8 + dc] * scale;

    float o[8];
    #pragma unroll
    for (int i = 0; i < 8; i++) o[i] = 0.f;
    float m = -1e30f, l = 0.f;

    for (int kt = 0; kt < SEQ; kt += 64) {
        // stage K,V tiles (64x64 each): 1024 float4, 256 threads -> 4 each
        #pragma unroll
        for (int j = 0; j < 4; j++) {
            int e  = tid + j * 256;
            int r  = e >> 4;
            int c4 = (e & 15) * 4;
            *(float4*)&Ks[r][c4] = *(const float4*)&Kg[(size_t)(kt + r) * DQKV + c4];
            *(float4*)&Vs[r][c4] = *(const float4*)&Vg[(size_t)(kt + r) * DQKV + c4];
        }
        __syncthreads();

        // S = q . k (partial over 8 owned d's), then 8-lane butterfly reduce
        float s[64];
        #pragma unroll
        for (int k = 0; k < 64; k++) {
            float p = 0.f;
            #pragma unroll
            for (int i = 0; i < 8; i++) p += qr[i] * Ks[k][i * 8 + dc];
            s[k] = p;
        }
        #pragma unroll
        for (int k = 0; k < 64; k++) {
            s[k] += __shfl_xor_sync(0xffffffffu, s[k], 1);
            s[k] += __shfl_xor_sync(0xffffffffu, s[k], 2);
            s[k] += __shfl_xor_sync(0xffffffffu, s[k], 4);
        }
        // online softmax (all 8 lanes hold identical full rows -> identical m,l)
        float mt = m;
        #pragma unroll
        for (int k = 0; k < 64; k++) mt = fmaxf(mt, s[k]);
        const float corr = __expf(m - mt);
        m = mt;
        l *= corr;
        #pragma unroll
        for (int i = 0; i < 8; i++) o[i] *= corr;

        float lsum = 0.f;
        #pragma unroll
        for (int k = 0; k < 64; k++) {
            s[k] = __expf(s[k] - m);
            lsum += s[k];
        }
        l += lsum;

        // O += P @ V  (each lane updates its owned d's)
        #pragma unroll
        for (int k = 0; k < 64; k++) {
            const float p = s[k];
            #pragma unroll
            for (int i = 0; i < 8; i++)
                o[i] += p * Vs[k][i * 8 + dc];
        }
        __syncthreads();
    }

    const float inv = 1.0f / l;
    float* Cp = ctx + ((size_t)b * SEQ + q0 + ql) * DM + h * 64;
    #pragma unroll
    for (int i = 0; i < 8; i++)
        Cp[i * 8 + dc] = o[i] * inv;
}

// ---------------- launch ----------------
extern "C" void kernel_launch(void* const* d_in, const int* in_sizes, int n_in,
                              void* d_out, int out_size) {
    const float* x     = (const float*)d_in[0];
    const float* qkv_w = (const float*)d_in[1];
    const float* qkv_b = (const float*)d_in[2];
    const float* out_w = (const float*)d_in[3];
    const float* out_b = (const float*)d_in[4];
    const float* ff1_w = (const float*)d_in[5];
    const float* ff1_b = (const float*)d_in[6];
    const float* ff2_w = (const float*)d_in[7];
    const float* ff2_b = (const float*)d_in[8];
    const float* ln1_g = (const float*)d_in[9];
    const float* ln1_b = (const float*)d_in[10];
    const float* ln2_g = (const float*)d_in[11];
    const float* ln2_b = (const float*)d_in[12];
    float* out = (float*)d_out;

    float *h, *qkv, *ctx, *x1, *h2, *ff;
    cudaGetSymbolAddress((void**)&h,   g_h);
    cudaGetSymbolAddress((void**)&qkv, g_qkv);
    cudaGetSymbolAddress((void**)&ctx, g_ctx);
    cudaGetSymbolAddress((void**)&x1,  g_x1);
    cudaGetSymbolAddress((void**)&h2,  g_h2);
    cudaGetSymbolAddress((void**)&ff,  g_ff);

    // 1. LN1
    ln_kernel<<<TOK, 256>>>(x, ln1_g, ln1_b, h);
    // 2. QKV projection [8192,1024]@[1024,3072]
    sgemm_kernel<0><<<dim3(DQKV / 128, TOK / 128), 256>>>(h, qkv_w, qkv_b, nullptr, qkv, TOK, DQKV, DM);
    // 3. attention
    attn_kernel<<<dim3(SEQ / 32, NHEAD, BATCH), 256>>>(qkv, ctx);
    // 4. out projection + residual  [8192,1024]@[1024,1024] + x
    sgemm_kernel<1><<<dim3(DM / 128, TOK / 128), 256>>>(ctx, out_w, out_b, x, x1, TOK, DM, DM);
    // 5. LN2
    ln_kernel<<<TOK, 256>>>(x1, ln2_g, ln2_b, h2);
    // 6. FF1 + GELU  [8192,1024]@[1024,2048]
    sgemm_kernel<2><<<dim3(DFF / 128, TOK / 128), 256>>>(h2, ff1_w, ff1_b, nullptr, ff, TOK, DFF, DM);
    // 7. FF2 + residual  [8192,2048]@[2048,1024] + x1 -> out
    sgemm_kernel<1><<<dim3(DM / 128, TOK / 128), 256>>>(ff, ff2_w, ff2_b, x1, out, TOK, DM, DFF);
}

// round 3
// speedup vs baseline: 4.1662x; 4.1633x over previous
#include <cuda_runtime.h>
#include <cuda_bf16.h>
#include <math.h>

#define TOK   8192
#define DM    1024
#define DQKV  3072
#define DFF   2048
#define SEQ   2048

// ---------------- scratch planes (device globals: allocation-free) ----------------
__device__ __nv_bfloat16 g_h1h[TOK*DM],   g_h1l[TOK*DM];     // LN1 out
__device__ __nv_bfloat16 g_qkh[TOK*DQKV], g_qkl[TOK*DQKV];   // qkv (Q pre-scaled)
__device__ __nv_bfloat16 g_cxh[TOK*DM],   g_cxl[TOK*DM];     // attn ctx
__device__ __nv_bfloat16 g_h2h[TOK*DM],   g_h2l[TOK*DM];     // LN2 out
__device__ __nv_bfloat16 g_ffh[TOK*DFF],  g_ffl[TOK*DFF];    // ff1 out (post-GELU)
__device__ float         g_x1 [TOK*DM];                      // residual1 fp32
__device__ __nv_bfloat16 g_wqh[DM*DQKV],  g_wql[DM*DQKV];
__device__ __nv_bfloat16 g_woh[DM*DM],    g_wol[DM*DM];
__device__ __nv_bfloat16 g_w1h[DM*DFF],   g_w1l[DM*DFF];
__device__ __nv_bfloat16 g_w2h[DFF*DM],   g_w2l[DFF*DM];

// ---------------- helpers ----------------
__device__ __forceinline__ unsigned pk2(float lo, float hi) {   // lo -> bits[15:0]
    unsigned d;
    asm("cvt.rn.bf16x2.f32 %0, %1, %2;" : "=r"(d) : "f"(hi), "f"(lo));
    return d;
}
__device__ __forceinline__ void split_store(__nv_bfloat16* H, __nv_bfloat16* L,
                                            size_t off, float x0, float x1) {
    float h0 = __bfloat162float(__float2bfloat16(x0));
    float h1 = __bfloat162float(__float2bfloat16(x1));
    *(unsigned*)((char*)H + off*2) = pk2(h0, h1);
    *(unsigned*)((char*)L + off*2) = pk2(x0 - h0, x1 - h1);
}
__device__ __forceinline__ void split_pk(float x0, float x1, unsigned& hp, unsigned& lp) {
    float h0 = __bfloat162float(__float2bfloat16(x0));
    float h1 = __bfloat162float(__float2bfloat16(x1));
    hp = pk2(h0, h1);
    lp = pk2(x0 - h0, x1 - h1);
}
__device__ __forceinline__ void ldsm4(unsigned& r0, unsigned& r1, unsigned& r2, unsigned& r3, unsigned a) {
    asm volatile("ldmatrix.sync.aligned.m8n8.x4.shared.b16 {%0,%1,%2,%3}, [%4];"
                 : "=r"(r0), "=r"(r1), "=r"(r2), "=r"(r3) : "r"(a));
}
__device__ __forceinline__ void ldsm2(unsigned& r0, unsigned& r1, unsigned a) {
    asm volatile("ldmatrix.sync.aligned.m8n8.x2.shared.b16 {%0,%1}, [%2];"
                 : "=r"(r0), "=r"(r1) : "r"(a));
}
__device__ __forceinline__ void ldsm2t(unsigned& r0, unsigned& r1, unsigned a) {
    asm volatile("ldmatrix.sync.aligned.m8n8.x2.trans.shared.b16 {%0,%1}, [%2];"
                 : "=r"(r0), "=r"(r1) : "r"(a));
}
__device__ __forceinline__ void mma16816(float* c, const unsigned* a, const unsigned* b) {
    asm volatile("mma.sync.aligned.m16n8k16.row.col.f32.bf16.bf16.f32 "
                 "{%0,%1,%2,%3},{%4,%5,%6,%7},{%8,%9},{%0,%1,%2,%3};"
                 : "+f"(c[0]), "+f"(c[1]), "+f"(c[2]), "+f"(c[3])
                 : "r"(a[0]), "r"(a[1]), "r"(a[2]), "r"(a[3]), "r"(b[0]), "r"(b[1]));
}
#define CPA(dst, src) asm volatile("cp.async.cg.shared.global [%0], [%1], 16;" ::"r"(dst), "l"(src))
#define CPC()         asm volatile("cp.async.commit_group;")
#define CPW(n)        asm volatile("cp.async.wait_group %0;" ::"n"(n))

// ---------------- weight split:  W fp32 -> hi/lo bf16 planes ----------------
__global__ void wconv(const float* __restrict__ W, __nv_bfloat16* __restrict__ H,
                      __nv_bfloat16* __restrict__ L, int n4) {
    int i = blockIdx.x * 256 + threadIdx.x;
    if (i >= n4) return;
    float4 v = ((const float4*)W)[i];
    split_store(H, L, (size_t)i * 4,     v.x, v.y);
    split_store(H, L, (size_t)i * 4 + 2, v.z, v.w);
}

// ---------------- LayerNorm -> hi/lo planes ----------------
__global__ void ln_kernel(const float* __restrict__ x, const float* __restrict__ gam,
                          const float* __restrict__ bet,
                          __nv_bfloat16* __restrict__ H, __nv_bfloat16* __restrict__ L) {
    const int row = blockIdx.x;
    const int t   = threadIdx.x;
    const float* xr = x + (size_t)row * DM;
    const int c0 = t * 4;
    float4 v = *(const float4*)(xr + c0);
    float s  = v.x + v.y + v.z + v.w;
    float ss = v.x*v.x + v.y*v.y + v.z*v.z + v.w*v.w;
    #pragma unroll
    for (int o = 16; o; o >>= 1) {
        s  += __shfl_xor_sync(0xffffffffu, s,  o);
        ss += __shfl_xor_sync(0xffffffffu, ss, o);
    }
    __shared__ float sm[8], sm2[8];
    const int w = t >> 5;
    if ((t & 31) == 0) { sm[w] = s; sm2[w] = ss; }
    __syncthreads();
    if (w == 0) {
        float a = (t < 8) ? sm[t] : 0.f;
        float c = (t < 8) ? sm2[t] : 0.f;
        #pragma unroll
        for (int o = 4; o; o >>= 1) {
            a += __shfl_xor_sync(0xffffffffu, a, o);
            c += __shfl_xor_sync(0xffffffffu, c, o);
        }
        if (t == 0) {
            float mu = a * (1.0f / DM);
            float var = c * (1.0f / DM) - mu * mu;
            sm[0] = mu; sm2[0] = rsqrtf(var + 1e-5f);
        }
    }
    __syncthreads();
    const float mu = sm[0], rs = sm2[0];
    float4 g4 = *(const float4*)(gam + c0);
    float4 b4 = *(const float4*)(bet + c0);
    float o0 = (v.x - mu) * rs * g4.x + b4.x;
    float o1 = (v.y - mu) * rs * g4.y + b4.y;
    float o2 = (v.z - mu) * rs * g4.z + b4.z;
    float o3 = (v.w - mu) * rs * g4.w + b4.w;
    size_t off = (size_t)row * DM + c0;
    split_store(H, L, off,     o0, o1);
    split_store(H, L, off + 2, o2, o3);
}

// ---------------- split-bf16 tensor-core GEMM ----------------
// C[M,N] = A[M,K] @ B[K,N] (+bias...). A,B given as hi/lo bf16 planes.
// 128x128 block, BK=16, 3-stage cp.async. 8 warps = 2(m) x 4(n); warptile 64x32.
// EPI: 0 = bias (+0.125 scale on cols<1024) -> planes; 1 = bias+res -> fp32; 2 = bias+GELU -> planes
template<int EPI>
__global__ __launch_bounds__(256, 2)
void mgemm(const __nv_bfloat16* __restrict__ Ah, const __nv_bfloat16* __restrict__ Al,
           const __nv_bfloat16* __restrict__ Bh, const __nv_bfloat16* __restrict__ Bl,
           const float* __restrict__ bias, const float* __restrict__ res,
           float* __restrict__ outF, __nv_bfloat16* __restrict__ outH, __nv_bfloat16* __restrict__ outL,
           int M, int N, int K) {
    // stage layout (16KB): A[0,8K): row m/2 (128B = m-even|m-odd, each 16k x 2 planes),
    //                      Bh[8K,12K), Bl[12K,16K): row k (256B = 128 n)
    __shared__ char smem[49152];
    const unsigned sbase = (unsigned)__cvta_generic_to_shared(smem);
    const int tid = threadIdx.x;
    const int rb = blockIdx.y << 7, cb = blockIdx.x << 7;

    // staging descriptors: 2 A-chunks + 2 B-chunks of 16B per thread per stage
    const __nv_bfloat16* aS[2]; unsigned aD[2];
    const __nv_bfloat16* bS[2]; unsigned bD[2];
    #pragma unroll
    for (int j = 0; j < 2; j++) {
        int ca = tid + j * 256;
        int m = ca & 127, f = ca >> 7;          // f: p = f>>1, kc = f&1
        int p = f >> 1, kc = f & 1;
        aS[j] = (p ? Al : Ah) + (size_t)(rb + m) * K + kc * 8;
        aD[j] = (m >> 1) * 128 + ((((m & 1) * 4) + p * 2 + kc) ^ ((m >> 1) & 7)) * 16;
        int nc = ca & 15, k = (ca >> 4) & 15, p2 = ca >> 8;
        bS[j] = (p2 ? Bl : Bh) + (size_t)k * N + cb + nc * 8;
        bD[j] = 8192 + p2 * 4096 + k * 256 + ((nc ^ (k & 7)) * 16);
    }
    const int nk = K >> 4;

    #define G_ISSUE(st, i) do { unsigned _b = sbase + (st) * 16384;                      \
        CPA(_b + aD[0], aS[0] + (i) * 16);  CPA(_b + aD[1], aS[1] + (i) * 16);           \
        CPA(_b + bD[0], bS[0] + (size_t)(i) * 16 * N);                                   \
        CPA(_b + bD[1], bS[1] + (size_t)(i) * 16 * N);  CPC(); } while (0)

    G_ISSUE(0, 0);
    G_ISSUE(1, 1);

    const int wid = tid >> 5, lane = tid & 31;
    const int wm = (wid >> 2) * 64, wn = (wid & 3) * 32;
    const int arl = (lane & 7) + 8 * ((lane >> 3) & 1);   // A ldsm row-in-tile
    const int akc = (lane >> 4) & 1;                       // A ldsm k-chunk
    const int brow = lane & 15;                            // B ldsm k-row

    float acc[4][4][4];
    #pragma unroll
    for (int a = 0; a < 4; a++)
        #pragma unroll
        for (int b = 0; b < 4; b++)
            #pragma unroll
            for (int e = 0; e < 4; e++) acc[a][b][e] = 0.f;

    for (int i = 0; i < nk; i++) {
        if (i == nk - 1) { CPW(0); } else { CPW(1); }
        __syncthreads();
        if (i + 2 < nk) {
            int st = (i + 2) % 3;
            G_ISSUE(st, i + 2);
        }
        const unsigned stb = sbase + (i % 3) * 16384;

        unsigned bh[4][2], bl[4][2];
        #pragma unroll
        for (int nt = 0; nt < 4; nt++) {
            int nc = (wn + nt * 8) >> 3;
            unsigned ad = stb + 8192 + brow * 256 + ((nc ^ (brow & 7)) * 16);
            ldsm2t(bh[nt][0], bh[nt][1], ad);
            ldsm2t(bl[nt][0], bl[nt][1], ad + 4096);
        }
        #pragma unroll
        for (int mt = 0; mt < 4; mt++) {
            int m = wm + mt * 16 + arl;
            unsigned base = stb + (m >> 1) * 128;
            unsigned Af[4], Lf[4];
            ldsm4(Af[0], Af[1], Af[2], Af[3], base + ((((m & 1) * 4) + akc)     ^ ((m >> 1) & 7)) * 16);
            ldsm4(Lf[0], Lf[1], Lf[2], Lf[3], base + ((((m & 1) * 4) + 2 + akc) ^ ((m >> 1) & 7)) * 16);
            #pragma unroll
            for (int nt = 0; nt < 4; nt++) {
                mma16816(acc[mt][nt], Af, bh[nt]);
                mma16816(acc[mt][nt], Af, bl[nt]);
                mma16816(acc[mt][nt], Lf, bh[nt]);
            }
        }
        __syncthreads();
    }

    // epilogue
    const float qs = (EPI == 0 && cb < 1024) ? 0.125f : 1.0f;
    #pragma unroll
    for (int mt = 0; mt < 4; mt++) {
        #pragma unroll
        for (int nt = 0; nt < 4; nt++) {
            int gr0 = rb + wm + mt * 16 + (lane >> 2);
            int gc  = cb + wn + nt * 8 + (lane & 3) * 2;
            float b0 = bias[gc], b1 = bias[gc + 1];
            #pragma unroll
            for (int hf = 0; hf < 2; hf++) {
                int gr = gr0 + hf * 8;
                float v0 = acc[mt][nt][hf * 2 + 0] + b0;
                float v1 = acc[mt][nt][hf * 2 + 1] + b1;
                size_t off = (size_t)gr * N + gc;
                if (EPI == 0) {
                    split_store(outH, outL, off, v0 * qs, v1 * qs);
                } else if (EPI == 1) {
                    v0 += res[off]; v1 += res[off + 1];
                    outF[off] = v0; outF[off + 1] = v1;
                } else {
                    v0 = 0.5f * v0 * (1.0f + erff(v0 * 0.70710678118654752f));
                    v1 = 0.5f * v1 * (1.0f + erff(v1 * 0.70710678118654752f));
                    split_store(outH, outL, off, v0, v1);
                }
            }
        }
    }
    #undef G_ISSUE
}

// ---------------- tensor-core flash attention ----------------
// block = 128 thr (4 warps) handles (b, h, 64 queries); key tiles of 32, double-buffered.
__global__ __launch_bounds__(128, 3)
void attn_kernel(const __nv_bfloat16* __restrict__ Ph, const __nv_bfloat16* __restrict__ Pl,
                 __nv_bfloat16* __restrict__ Oh, __nv_bfloat16* __restrict__ Ol) {
    // smem: [0,16K): Q (64 rows x 256B = 64d x 2 planes); [16K,32K)+[32K,48K): KV stages
    // KV stage: Kh[0,4K) Kl[4K,8K) Vh[8K,12K) Vl[12K,16K); rows of 128B (64 d)
    __shared__ char smem[49152];
    const unsigned sbase = (unsigned)__cvta_generic_to_shared(smem);
    const int b = blockIdx.z, hh = blockIdx.y, q0 = blockIdx.x * 64;
    const int tid = threadIdx.x, wid = tid >> 5, lane = tid & 31;

    // ---- stage Q ----
    #pragma unroll
    for (int j = 0; j < 8; j++) {
        int qc = tid + j * 128;
        int row = qc & 63, rest = qc >> 6;
        int dc = rest & 7, p = rest >> 3;
        const __nv_bfloat16* src = (p ? Pl : Ph) + (size_t)(b * SEQ + q0 + row) * DQKV + hh * 64 + dc * 8;
        *(uint4*)(smem + row * 256 + (((dc ^ (row & 7)) + p * 8) * 16)) = *(const uint4*)src;
    }
    __syncthreads();

    const int arl = (lane & 7) + 8 * ((lane >> 3) & 1);
    const int akc = (lane >> 4) & 1;
    unsigned qf[4][2][4];
    #pragma unroll
    for (int kc = 0; kc < 4; kc++)
        #pragma unroll
        for (int p = 0; p < 2; p++) {
            int row = wid * 16 + arl;
            int dc = kc * 2 + akc;
            unsigned ad = sbase + row * 256 + (((dc ^ (row & 7)) + p * 8) * 16);
            ldsm4(qf[kc][p][0], qf[kc][p][1], qf[kc][p][2], qf[kc][p][3], ad);
        }

    // ---- KV staging descriptors: 8 chunks / thread / stage ----
    const __nv_bfloat16* kvS[8]; unsigned kvD[8];
    #pragma unroll
    for (int j = 0; j < 8; j++) {
        int cc = tid + j * 128;
        int dc = cc & 7, key = (cc >> 3) & 31, rest = cc >> 8;
        int p = rest & 1, mat = rest >> 1;   // mat: 0=K,1=V
        kvS[j] = (p ? Pl : Ph) + (size_t)(b * SEQ + key) * DQKV + 1024 + mat * 1024 + hh * 64 + dc * 8;
        kvD[j] = (mat * 2 + p) * 4096 + key * 128 + ((dc ^ (key & 7)) * 16);
    }
    #define A_ISSUE(t) do { unsigned _b = sbase + 16384 + ((t) & 1) * 16384;             \
        _Pragma("unroll") for (int j = 0; j < 8; j++)                                    \
            CPA(_b + kvD[j], kvS[j] + (size_t)(t) * 32 * DQKV);                          \
        CPC(); } while (0)

    A_ISSUE(0);

    float o[8][4];
    #pragma unroll
    for (int i = 0; i < 8; i++)
        #pragma unroll
        for (int e = 0; e < 4; e++) o[i][e] = 0.f;
    float m0 = -1e30f, m1 = -1e30f, l0 = 0.f, l1 = 0.f;

    for (int t = 0; t < SEQ / 32; t++) {
        if (t + 1 < SEQ / 32) { A_ISSUE(t + 1); CPW(1); } else { CPW(0); }
        __syncthreads();
        const unsigned stb = sbase + 16384 + (t & 1) * 16384;

        // S = Q K^T  (16x32 per warp)
        float s[4][4];
        #pragma unroll
        for (int nt = 0; nt < 4; nt++)
            #pragma unroll
            for (int e = 0; e < 4; e++) s[nt][e] = 0.f;
        {
            int row = (lane & 7);       // combined below with nt
            int kch = ((lane >> 3) & 1);
            #pragma unroll
            for (int kc = 0; kc < 4; kc++) {
                #pragma unroll
                for (int nt = 0; nt < 4; nt++) {
                    int r = nt * 8 + row;
                    int chunk = kc * 2 + kch;
                    unsigned kd = stb + r * 128 + ((chunk ^ (r & 7)) * 16);
                    unsigned kh[2], kl[2];
                    ldsm2(kh[0], kh[1], kd);
                    ldsm2(kl[0], kl[1], kd + 4096);
                    mma16816(s[nt], qf[kc][0], kh);
                    mma16816(s[nt], qf[kc][0], kl);
                    mma16816(s[nt], qf[kc][1], kh);
                }
            }
        }
        // online softmax (rows: lo = t/4, hi = t/4+8)
        float mx0 = -1e30f, mx1 = -1e30f;
        #pragma unroll
        for (int nt = 0; nt < 4; nt++) {
            mx0 = fmaxf(mx0, fmaxf(s[nt][0], s[nt][1]));
            mx1 = fmaxf(mx1, fmaxf(s[nt][2], s[nt][3]));
        }
        mx0 = fmaxf(mx0, __shfl_xor_sync(0xffffffffu, mx0, 1));
        mx0 = fmaxf(mx0, __shfl_xor_sync(0xffffffffu, mx0, 2));
        mx1 = fmaxf(mx1, __shfl_xor_sync(0xffffffffu, mx1, 1));
        mx1 = fmaxf(mx1, __shfl_xor_sync(0xffffffffu, mx1, 2));
        float mn0 = fmaxf(m0, mx0), mn1 = fmaxf(m1, mx1);
        float c0 = __expf(m0 - mn0), c1 = __expf(m1 - mn1);
        m0 = mn0; m1 = mn1;
        l0 *= c0; l1 *= c1;
        #pragma unroll
        for (int nt = 0; nt < 4; nt++) {
            s[nt][0] = __expf(s[nt][0] - m0); l0 += s[nt][0];
            s[nt][1] = __expf(s[nt][1] - m0); l0 += s[nt][1];
            s[nt][2] = __expf(s[nt][2] - m1); l1 += s[nt][2];
            s[nt][3] = __expf(s[nt][3] - m1); l1 += s[nt][3];
        }
        #pragma unroll
        for (int nt = 0; nt < 8; nt++) {
            o[nt][0] *= c0; o[nt][1] *= c0; o[nt][2] *= c1; o[nt][3] *= c1;
        }
        // P fragments (C layout == A layout for PV)
        unsigned ph[2][4], pl[2][4];
        #pragma unroll
        for (int kc2 = 0; kc2 < 2; kc2++) {
            split_pk(s[2 * kc2][0],     s[2 * kc2][1],     ph[kc2][0], pl[kc2][0]);
            split_pk(s[2 * kc2][2],     s[2 * kc2][3],     ph[kc2][1], pl[kc2][1]);
            split_pk(s[2 * kc2 + 1][0], s[2 * kc2 + 1][1], ph[kc2][2], pl[kc2][2]);
            split_pk(s[2 * kc2 + 1][2], s[2 * kc2 + 1][3], ph[kc2][3], pl[kc2][3]);
        }
        // O += P V
        #pragma unroll
        for (int kc2 = 0; kc2 < 2; kc2++) {
            int row = kc2 * 16 + (lane & 15);
            #pragma unroll
            for (int nt = 0; nt < 8; nt++) {
                unsigned vd = stb + 8192 + row * 128 + ((nt ^ (row & 7)) * 16);
                unsigned vh[2], vl[2];
                ldsm2t(vh[0], vh[1], vd);
                ldsm2t(vl[0], vl[1], vd + 4096);
                mma16816(o[nt], ph[kc2], vh);
                mma16816(o[nt], ph[kc2], vl);
                mma16816(o[nt], pl[kc2], vh);
            }
        }
        __syncthreads();
    }

    l0 += __shfl_xor_sync(0xffffffffu, l0, 1);
    l0 += __shfl_xor_sync(0xffffffffu, l0, 2);
    l1 += __shfl_xor_sync(0xffffffffu, l1, 1);
    l1 += __shfl_xor_sync(0xffffffffu, l1, 2);
    const float i0 = 1.0f / l0, i1 = 1.0f / l1;
    const int r0 = q0 + wid * 16 + (lane >> 2);
    #pragma unroll
    for (int nt = 0; nt < 8; nt++) {
        int d = nt * 8 + (lane & 3) * 2;
        split_store(Oh, Ol, (size_t)(b * SEQ + r0) * DM + hh * 64 + d,     o[nt][0] * i0, o[nt][1] * i0);
        split_store(Oh, Ol, (size_t)(b * SEQ + r0 + 8) * DM + hh * 64 + d, o[nt][2] * i1, o[nt][3] * i1);
    }
    #undef A_ISSUE
}

// ---------------- launch ----------------
extern "C" void kernel_launch(void* const* d_in, const int* in_sizes, int n_in,
                              void* d_out, int out_size) {
    const float* x     = (const float*)d_in[0];
    const float* qkv_w = (const float*)d_in[1];
    const float* qkv_b = (const float*)d_in[2];
    const float* out_w = (const float*)d_in[3];
    const float* out_b = (const float*)d_in[4];
    const float* ff1_w = (const float*)d_in[5];
    const float* ff1_b = (const float*)d_in[6];
    const float* ff2_w = (const float*)d_in[7];
    const float* ff2_b = (const float*)d_in[8];
    const float* ln1_g = (const float*)d_in[9];
    const float* ln1_b = (const float*)d_in[10];
    const float* ln2_g = (const float*)d_in[11];
    const float* ln2_b = (const float*)d_in[12];
    float* out = (float*)d_out;

    __nv_bfloat16 *h1h, *h1l, *qkh, *qkl, *cxh, *cxl, *h2h, *h2l, *ffh, *ffl;
    __nv_bfloat16 *wqh, *wql, *woh, *wol, *w1h, *w1l, *w2h, *w2l;
    float* x1;
    cudaGetSymbolAddress((void**)&h1h, g_h1h); cudaGetSymbolAddress((void**)&h1l, g_h1l);
    cudaGetSymbolAddress((void**)&qkh, g_qkh); cudaGetSymbolAddress((void**)&qkl, g_qkl);
    cudaGetSymbolAddress((void**)&cxh, g_cxh); cudaGetSymbolAddress((void**)&cxl, g_cxl);
    cudaGetSymbolAddress((void**)&h2h, g_h2h); cudaGetSymbolAddress((void**)&h2l, g_h2l);
    cudaGetSymbolAddress((void**)&ffh, g_ffh); cudaGetSymbolAddress((void**)&ffl, g_ffl);
    cudaGetSymbolAddress((void**)&wqh, g_wqh); cudaGetSymbolAddress((void**)&wql, g_wql);
    cudaGetSymbolAddress((void**)&woh, g_woh); cudaGetSymbolAddress((void**)&wol, g_wol);
    cudaGetSymbolAddress((void**)&w1h, g_w1h); cudaGetSymbolAddress((void**)&w1l, g_w1l);
    cudaGetSymbolAddress((void**)&w2h, g_w2h); cudaGetSymbolAddress((void**)&w2l, g_w2l);
    cudaGetSymbolAddress((void**)&x1,  g_x1);

    // weight splits
    wconv<<<(DM * DQKV / 4 + 255) / 256, 256>>>(qkv_w, wqh, wql, DM * DQKV / 4);
    wconv<<<(DM * DM   / 4 + 255) / 256, 256>>>(out_w, woh, wol, DM * DM / 4);
    wconv<<<(DM * DFF  / 4 + 255) / 256, 256>>>(ff1_w, w1h, w1l, DM * DFF / 4);
    wconv<<<(DFF * DM  / 4 + 255) / 256, 256>>>(ff2_w, w2h, w2l, DFF * DM / 4);

    // 1. LN1 -> planes
    ln_kernel<<<TOK, 256>>>(x, ln1_g, ln1_b, h1h, h1l);
    // 2. QKV projection (Q pre-scaled by 0.125) -> planes
    mgemm<0><<<dim3(DQKV / 128, TOK / 128), 256>>>(h1h, h1l, wqh, wql, qkv_b, nullptr,
                                                   nullptr, qkh, qkl, TOK, DQKV, DM);
    // 3. attention -> ctx planes
    attn_kernel<<<dim3(SEQ / 64, 16, 4), 128>>>(qkh, qkl, cxh, cxl);
    // 4. out projection + residual -> x1 (fp32)
    mgemm<1><<<dim3(DM / 128, TOK / 128), 256>>>(cxh, cxl, woh, wol, out_b, x,
                                                 x1, nullptr, nullptr, TOK, DM, DM);
    // 5. LN2 -> planes
    ln_kernel<<<TOK, 256>>>(x1, ln2_g, ln2_b, h2h, h2l);
    // 6. FF1 + exact GELU -> planes
    mgemm<2><<<dim3(DFF / 128, TOK / 128), 256>>>(h2h, h2l, w1h, w1l, ff1_b, nullptr,
                                                  nullptr, ffh, ffl, TOK, DFF, DM);
    // 7. FF2 + residual -> out (fp32)
    mgemm<1><<<dim3(DM / 128, TOK / 128), 256>>>(ffh, ffl, w2h, w2l, ff2_b, x1,
                                                 out, nullptr, nullptr, TOK, DM, DFF);
}